// round 15
// baseline (speedup 1.0000x reference)
#include <cuda_runtime.h>
#include <math.h>

// ---------------- problem constants ----------------
#define BATCH   32
#define IMGHW   56
#define CH      192
#define HEADS   6
#define HDIM    32
#define WSZ     7
#define NTOK    49
#define NWIN    64
#define BW      (BATCH*NWIN)     // 2048 windows
#define MROWS   (BW*NTOK)        // 100352 tokens
#define MLPH    768

// ---------------- scratch ----------------
__device__ float g_q[BW*HEADS*NTOK*HDIM];
__device__ float g_k[BW*HEADS*NTOK*HDIM];
__device__ float g_v[BW*HEADS*NTOK*HDIM];
__device__ float g_attnout[MROWS*CH];
__device__ float g_x1[MROWS*CH];
__device__ float g_hidden[MROWS*MLPH];
__device__ float g_rpb[HEADS*NTOK*NTOK];

__device__ __forceinline__ int row_to_pix(int m){
    int b_ = m / NTOK;
    int nn = m - b_*NTOK;
    int b  = b_ >> 6;
    int w  = b_ & 63;
    int wh = w >> 3, ww = w & 7;
    int r  = nn / 7, c = nn - r*7;
    int h  = wh*7 + r + 3; if (h >= IMGHW) h -= IMGHW;
    int x  = ww*7 + c + 3; if (x >= IMGHW) x -= IMGHW;
    return ((b*IMGHW + h)*IMGHW + x)*CH;
}

// ---------------- tf32 helpers ----------------
__device__ __forceinline__ unsigned tf32r(float x){
    unsigned u; asm("cvt.rna.tf32.f32 %0, %1;" : "=r"(u) : "f"(x)); return u;
}
__device__ __forceinline__ void mma8(float* c, const unsigned* a, const unsigned* b){
    asm volatile("mma.sync.aligned.m16n8k8.row.col.f32.tf32.tf32.f32 "
        "{%0,%1,%2,%3},{%4,%5,%6,%7},{%8,%9},{%0,%1,%2,%3};"
        : "+f"(c[0]), "+f"(c[1]), "+f"(c[2]), "+f"(c[3])
        : "r"(a[0]), "r"(a[1]), "r"(a[2]), "r"(a[3]), "r"(b[0]), "r"(b[1]));
}

// fast erf (Abramowitz & Stegun 7.1.26, |err| < 1.5e-7)
__device__ __forceinline__ float erf_fast(float x){
    float ax = fabsf(x);
    float t  = 1.0f / (1.0f + 0.3275911f * ax);
    float p  = t*(0.254829592f + t*(-0.284496736f + t*(1.421413741f +
               t*(-1.453152027f + t*1.061405429f))));
    float e  = 1.0f - p * __expf(-ax*ax);
    return copysignf(e, x);
}
__device__ __forceinline__ float gelu_fast(float x){
    return x * 0.5f * (1.0f + erf_fast(x * 0.70710678118654752f));
}

// ---------------- kernel 0: CPB MLP -> bias table ----------------
__global__ __launch_bounds__(256)
void cpb_kernel(const float* __restrict__ w1, const float* __restrict__ b1,
                const float* __restrict__ w2){
    __shared__ float tbl[169*HEADS];
    const int tid = threadIdx.x;
    if (tid < 169){
        int dh = tid / 13, dw = tid - 13*(tid/13);
        float th = (float)(dh - 6) / 6.0f * 7.0f;
        float tw = (float)(dw - 6) / 6.0f * 7.0f;
        float sh = (th > 0.f) ? 1.f : ((th < 0.f) ? -1.f : 0.f);
        float sw = (tw > 0.f) ? 1.f : ((tw < 0.f) ? -1.f : 0.f);
        const float inv_log2_7 = 1.0f / log2f(7.0f);
        th = sh * log2f(fabsf(th) + 1.0f) * inv_log2_7;
        tw = sw * log2f(fabsf(tw) + 1.0f) * inv_log2_7;
        float acc[HEADS];
        #pragma unroll
        for (int h = 0; h < HEADS; h++) acc[h] = 0.f;
        for (int j = 0; j < 512; j++){
            float hv = w1[j*2]*th + w1[j*2+1]*tw + b1[j];
            hv = (hv > 0.f) ? hv : 0.01f*hv;
            #pragma unroll
            for (int h = 0; h < HEADS; h++) acc[h] += w2[h*512 + j] * hv;
        }
        #pragma unroll
        for (int h = 0; h < HEADS; h++) tbl[tid*HEADS + h] = acc[h];
    }
    __syncthreads();
    for (int p = tid; p < HEADS*NTOK*NTOK; p += 256){
        int h   = p / (NTOK*NTOK);
        int rem = p - h*(NTOK*NTOK);
        int i   = rem / NTOK, j = rem - i*NTOK;
        int dh  = i/7 - j/7 + 6;
        int dw  = (i - 7*(i/7)) - (j - 7*(j/7)) + 6;
        float v = tbl[(dh*13 + dw)*HEADS + h];
        g_rpb[p] = 14.0f / (1.0f + expf(-v));
    }
}

// ---------------- kernel 1: QKV GEMM, pipelined ----------------
// SPLIT3=true: 3xTF32 hi/lo split (q,k columns). false: single-pass (v columns).
template<bool SPLIT3>
__global__ __launch_bounds__(256)
void qkv_kernel(const float* __restrict__ x, const float* __restrict__ w,
                const float* __restrict__ bias, int ny0){
    __shared__ float As[2][128][20];
    __shared__ float Bs[2][64][20];
    __shared__ int rpix[128];
    __shared__ int rq[128];
    const int tid  = threadIdx.x;
    const int m0   = blockIdx.x * 128;
    const int n0   = (blockIdx.y + ny0) * 64;
    const int warp = tid >> 5, lane = tid & 31;
    const int g = lane >> 2, t = lane & 3;
    const int warp_m = warp & 3, warp_n = warp >> 2;
    const int m_w = warp_m*32, n_w = warp_n*32;
    if (tid < 128){
        int m = m0 + tid;
        rpix[tid] = row_to_pix(m);
        int b_ = m / NTOK; int nn = m - b_*NTOK;
        rq[tid] = b_*(HEADS*NTOK*HDIM) + nn*HDIM;
    }
    const int rowA = tid >> 1, ka = (tid & 1) * 8;
    const int rowB = tid >> 2, kb = (tid & 3) * 4;
    float c[2][4][4];
    #pragma unroll
    for (int i=0;i<2;i++) for (int j=0;j<4;j++) for (int q=0;q<4;q++) c[i][j][q]=0.f;
    __syncthreads();
    const float* pA = x + rpix[rowA] + ka;
    const float* pB = w + (n0 + rowB)*CH + kb;
    {
        float4 a0 = *(const float4*)(pA);
        float4 a1 = *(const float4*)(pA + 4);
        float4 bv = *(const float4*)(pB);
        As[0][rowA][ka+0]=a0.x; As[0][rowA][ka+1]=a0.y; As[0][rowA][ka+2]=a0.z; As[0][rowA][ka+3]=a0.w;
        As[0][rowA][ka+4]=a1.x; As[0][rowA][ka+5]=a1.y; As[0][rowA][ka+6]=a1.z; As[0][rowA][ka+7]=a1.w;
        Bs[0][rowB][kb+0]=bv.x; Bs[0][rowB][kb+1]=bv.y; Bs[0][rowB][kb+2]=bv.z; Bs[0][rowB][kb+3]=bv.w;
    }
    __syncthreads();
    int p = 0;
    for (int kt = 0; kt < 12; kt++){
        float4 na0, na1, nbv;
        if (kt < 11){
            na0 = *(const float4*)(pA + (kt+1)*16);
            na1 = *(const float4*)(pA + (kt+1)*16 + 4);
            nbv = *(const float4*)(pB + (kt+1)*16);
        }
        #pragma unroll
        for (int ks = 0; ks < 2; ks++){
            const int k0 = ks*8;
            if (SPLIT3){
                unsigned ah[2][4], al[2][4];
                #pragma unroll
                for (int mi = 0; mi < 2; mi++){
                    int mr = m_w + mi*16;
                    float f;
                    f = As[p][mr+g][k0+t];     ah[mi][0]=tf32r(f); al[mi][0]=tf32r(f-__uint_as_float(ah[mi][0]));
                    f = As[p][mr+8+g][k0+t];   ah[mi][1]=tf32r(f); al[mi][1]=tf32r(f-__uint_as_float(ah[mi][1]));
                    f = As[p][mr+g][k0+t+4];   ah[mi][2]=tf32r(f); al[mi][2]=tf32r(f-__uint_as_float(ah[mi][2]));
                    f = As[p][mr+8+g][k0+t+4]; ah[mi][3]=tf32r(f); al[mi][3]=tf32r(f-__uint_as_float(ah[mi][3]));
                }
                unsigned bh[4][2], bl[4][2];
                #pragma unroll
                for (int ni = 0; ni < 4; ni++){
                    int nr = n_w + ni*8 + g;
                    float f;
                    f = Bs[p][nr][k0+t];   bh[ni][0]=tf32r(f); bl[ni][0]=tf32r(f-__uint_as_float(bh[ni][0]));
                    f = Bs[p][nr][k0+t+4]; bh[ni][1]=tf32r(f); bl[ni][1]=tf32r(f-__uint_as_float(bh[ni][1]));
                }
                #pragma unroll
                for (int mi = 0; mi < 2; mi++)
                    #pragma unroll
                    for (int ni = 0; ni < 4; ni++){
                        mma8(c[mi][ni], al[mi], bh[ni]);
                        mma8(c[mi][ni], ah[mi], bl[ni]);
                        mma8(c[mi][ni], ah[mi], bh[ni]);
                    }
            } else {
                unsigned a[2][4];
                #pragma unroll
                for (int mi = 0; mi < 2; mi++){
                    int mr = m_w + mi*16;
                    a[mi][0] = tf32r(As[p][mr+g][k0+t]);
                    a[mi][1] = tf32r(As[p][mr+8+g][k0+t]);
                    a[mi][2] = tf32r(As[p][mr+g][k0+t+4]);
                    a[mi][3] = tf32r(As[p][mr+8+g][k0+t+4]);
                }
                unsigned b[4][2];
                #pragma unroll
                for (int ni = 0; ni < 4; ni++){
                    int nr = n_w + ni*8 + g;
                    b[ni][0] = tf32r(Bs[p][nr][k0+t]);
                    b[ni][1] = tf32r(Bs[p][nr][k0+t+4]);
                }
                #pragma unroll
                for (int mi = 0; mi < 2; mi++)
                    #pragma unroll
                    for (int ni = 0; ni < 4; ni++)
                        mma8(c[mi][ni], a[mi], b[ni]);
            }
        }
        if (kt < 11){
            int q = 1-p;
            As[q][rowA][ka+0]=na0.x; As[q][rowA][ka+1]=na0.y; As[q][rowA][ka+2]=na0.z; As[q][rowA][ka+3]=na0.w;
            As[q][rowA][ka+4]=na1.x; As[q][rowA][ka+5]=na1.y; As[q][rowA][ka+6]=na1.z; As[q][rowA][ka+7]=na1.w;
            Bs[q][rowB][kb+0]=nbv.x; Bs[q][rowB][kb+1]=nbv.y; Bs[q][rowB][kb+2]=nbv.z; Bs[q][rowB][kb+3]=nbv.w;
            __syncthreads();
        }
        p ^= 1;
    }
    #pragma unroll
    for (int mi = 0; mi < 2; mi++){
        #pragma unroll
        for (int ni = 0; ni < 4; ni++){
            int col  = n0 + n_w + ni*8 + t*2;
            int slot = col / 192;
            int rem  = col - slot*192;
            float* dst = (slot == 0) ? g_q : ((slot == 1) ? g_k : g_v);
            int off = (rem >> 5)*(NTOK*HDIM) + (rem & 31);
            float2 bv = *(const float2*)(bias + col);
            int r0 = m_w + mi*16 + g;
            float2 o0 = {c[mi][ni][0] + bv.x, c[mi][ni][1] + bv.y};
            *(float2*)(dst + rq[r0] + off) = o0;
            float2 o1 = {c[mi][ni][2] + bv.x, c[mi][ni][3] + bv.y};
            *(float2*)(dst + rq[r0+8] + off) = o1;
        }
    }
}

// ---------------- kernel 2: windowed attention, tensor-core ----------------
// One block per (window, head). 256 threads, 8 warps.
// S = qn@kn^T via 3xTF32 (64x64x32), softmax in-place, O = P@V via 2xTF32 (64x32x64).
__global__ __launch_bounds__(256)
void attn_kernel(const float* __restrict__ logit_scale){
    __shared__ float qs[64*36];        // [n][d], stride 36 (conflict-free frags)
    __shared__ float ks[64*36];
    __shared__ float vs[64*40];        // [j][d], stride 40
    __shared__ float S[64*68];         // [i][j], stride 68
    __shared__ int lab[64];
    const int b_   = blockIdx.x;
    const int head = blockIdx.y;
    const int tid  = threadIdx.x;
    const int warp = tid >> 5, lane = tid & 31;
    const int g = lane >> 2, t = lane & 3;
    const float* qg = g_q + (b_*HEADS + head)*NTOK*HDIM;
    const float* kg = g_k + (b_*HEADS + head)*NTOK*HDIM;
    const float* vg = g_v + (b_*HEADS + head)*NTOK*HDIM;

    // load (pad rows 49..63 with zeros)
    for (int idx = tid; idx < 64*32; idx += 256){
        int n = idx >> 5, d = idx & 31;
        bool ok = (n < NTOK);
        float qv = ok ? qg[n*HDIM + d] : 0.f;
        float kv = ok ? kg[n*HDIM + d] : 0.f;
        float vv = ok ? vg[n*HDIM + d] : 0.f;
        qs[n*36 + d] = qv;
        ks[n*36 + d] = kv;
        vs[n*40 + d] = vv;
    }
    if (tid < NTOK){
        int w  = b_ & 63;
        int wh = w >> 3, ww = w & 7;
        int r  = tid / 7, c = tid - 7*r;
        int hp = wh*7 + r, wp = ww*7 + c;
        int rb = (hp < 49) ? 0 : ((hp < 53) ? 1 : 2);
        int cb = (wp < 49) ? 0 : ((wp < 53) ? 1 : 2);
        lab[tid] = rb*3 + cb;
    }
    __syncthreads();
    // cosine row-normalize q and k (rows < 49)
    if (tid < 2*NTOK){
        int i = (tid < NTOK) ? tid : tid - NTOK;
        float* base = ((tid < NTOK) ? qs : ks) + i*36;
        float ss = 0.f;
        #pragma unroll
        for (int d = 0; d < 32; d++){ float v = base[d]; ss += v*v; }
        float inv = 1.0f / fmaxf(sqrtf(ss), 1e-12f);
        #pragma unroll
        for (int d = 0; d < 32; d++) base[d] *= inv;
    }
    __syncthreads();
    // S = qn @ kn^T  (3xTF32). warp: rows 16*(w&3), cols 32*(w>>2)
    {
        const int mt = (warp & 3) * 16;
        const int nt = (warp >> 2) * 32;
        float c[4][4];
        #pragma unroll
        for (int i=0;i<4;i++) for (int j=0;j<4;j++) c[i][j]=0.f;
        #pragma unroll
        for (int k0 = 0; k0 < 32; k0 += 8){
            unsigned ah[4], al[4];
            float f;
            f = qs[(mt+g)*36 + k0+t];     ah[0]=tf32r(f); al[0]=tf32r(f-__uint_as_float(ah[0]));
            f = qs[(mt+8+g)*36 + k0+t];   ah[1]=tf32r(f); al[1]=tf32r(f-__uint_as_float(ah[1]));
            f = qs[(mt+g)*36 + k0+t+4];   ah[2]=tf32r(f); al[2]=tf32r(f-__uint_as_float(ah[2]));
            f = qs[(mt+8+g)*36 + k0+t+4]; ah[3]=tf32r(f); al[3]=tf32r(f-__uint_as_float(ah[3]));
            #pragma unroll
            for (int ni = 0; ni < 4; ni++){
                int nr = nt + ni*8 + g;
                unsigned bh[2], bl[2];
                f = ks[nr*36 + k0+t];   bh[0]=tf32r(f); bl[0]=tf32r(f-__uint_as_float(bh[0]));
                f = ks[nr*36 + k0+t+4]; bh[1]=tf32r(f); bl[1]=tf32r(f-__uint_as_float(bh[1]));
                mma8(c[ni], al, bh);
                mma8(c[ni], ah, bl);
                mma8(c[ni], ah, bh);
            }
        }
        #pragma unroll
        for (int ni = 0; ni < 4; ni++){
            int col = nt + ni*8 + 2*t;
            *(float2*)&S[(mt+g)*68 + col]   = make_float2(c[ni][0], c[ni][1]);
            *(float2*)&S[(mt+8+g)*68 + col] = make_float2(c[ni][2], c[ni][3]);
        }
    }
    __syncthreads();
    // softmax in place: P[i][j] for i<49; pad cols j>=49 set to 0
    if (tid < NTOK){
        int i = tid;
        const float sc = expf(fminf(logit_scale[head], 4.60517019f));
        const float* rpb = g_rpb + head*NTOK*NTOK + i*NTOK;
        float* row = S + i*68;
        int li = lab[i];
        float mx = -1e30f;
        for (int j = 0; j < NTOK; j++){
            float mval = (li == lab[j]) ? 0.f : -100.f;
            float v = row[j]*sc + rpb[j] + mval;
            row[j] = v;
            mx = fmaxf(mx, v);
        }
        float sum = 0.f;
        for (int j = 0; j < NTOK; j++){
            float e = __expf(row[j] - mx);
            row[j] = e;
            sum += e;
        }
        float inv = 1.0f / sum;
        for (int j = 0; j < NTOK; j++) row[j] *= inv;
        for (int j = NTOK; j < 64; j++) row[j] = 0.f;
    }
    __syncthreads();
    // O = P @ V  (P split hi/lo, V single tf32). warp: rows 16*(w&3), cols 16*(w>>2)
    {
        const int mt = (warp & 3) * 16;
        const int nh = (warp >> 2) * 16;
        float c[2][4];
        #pragma unroll
        for (int i=0;i<2;i++) for (int j=0;j<4;j++) c[i][j]=0.f;
        #pragma unroll
        for (int k0 = 0; k0 < 64; k0 += 8){
            unsigned ah[4], al[4];
            float f;
            f = S[(mt+g)*68 + k0+t];     ah[0]=tf32r(f); al[0]=tf32r(f-__uint_as_float(ah[0]));
            f = S[(mt+8+g)*68 + k0+t];   ah[1]=tf32r(f); al[1]=tf32r(f-__uint_as_float(ah[1]));
            f = S[(mt+g)*68 + k0+t+4];   ah[2]=tf32r(f); al[2]=tf32r(f-__uint_as_float(ah[2]));
            f = S[(mt+8+g)*68 + k0+t+4]; ah[3]=tf32r(f); al[3]=tf32r(f-__uint_as_float(ah[3]));
            #pragma unroll
            for (int ni = 0; ni < 2; ni++){
                unsigned b[2];
                b[0] = tf32r(vs[(k0+t)*40 + nh + ni*8 + g]);
                b[1] = tf32r(vs[(k0+t+4)*40 + nh + ni*8 + g]);
                mma8(c[ni], ah, b);
                mma8(c[ni], al, b);
            }
        }
        float* outb = g_attnout + (long)(b_*NTOK)*CH + head*HDIM;
        int r0 = mt + g, r1 = mt + 8 + g;
        #pragma unroll
        for (int ni = 0; ni < 2; ni++){
            int col = nh + ni*8 + 2*t;
            if (r0 < NTOK) *(float2*)&outb[r0*CH + col] = make_float2(c[ni][0], c[ni][1]);
            if (r1 < NTOK) *(float2*)&outb[r1*CH + col] = make_float2(c[ni][2], c[ni][3]);
        }
    }
}

// ---------------- kernels 3/5: GEMM(BMx192) + LN + residual (R4 version, runtime K) ----------------
template<bool PIX>
__global__ __launch_bounds__(256)
void gemm_ln_kernel(const float* __restrict__ A, const float* __restrict__ w,
                    const float* __restrict__ bias, const float* __restrict__ nw,
                    const float* __restrict__ nb, const float* __restrict__ res,
                    float* __restrict__ out, int K){
    __shared__ float As[2][64][20];
    __shared__ float Bs[2][192][20];
    __shared__ float red_s[64][4], red_q[64][4];
    __shared__ int rpix[64];
    const int tid  = threadIdx.x;
    const int m0   = blockIdx.x * 64;
    const int warp = tid >> 5, lane = tid & 31;
    const int g = lane >> 2, t = lane & 3;
    const int warp_m = warp >> 2, warp_n = warp & 3;
    const int m_w = warp_m*32, n_w = warp_n*48;
    if (PIX && tid < 64) rpix[tid] = row_to_pix(m0 + tid);
    const int rowA = tid >> 2, ka = (tid & 3) * 4;
    float c[2][6][4];
    #pragma unroll
    for (int i=0;i<2;i++) for (int j=0;j<6;j++) for (int q=0;q<4;q++) c[i][j][q]=0.f;

    const float* pA  = A + (long)(m0 + rowA)*K + ka;
    const float* pB0 = w + (long)(rowA      )*K + ka;
    const float* pB1 = w + (long)(rowA + 64 )*K + ka;
    const float* pB2 = w + (long)(rowA + 128)*K + ka;
    {
        float4 av  = *(const float4*)(pA);
        float4 bv0 = *(const float4*)(pB0);
        float4 bv1 = *(const float4*)(pB1);
        float4 bv2 = *(const float4*)(pB2);
        As[0][rowA][ka+0]=av.x; As[0][rowA][ka+1]=av.y; As[0][rowA][ka+2]=av.z; As[0][rowA][ka+3]=av.w;
        Bs[0][rowA][ka+0]=bv0.x; Bs[0][rowA][ka+1]=bv0.y; Bs[0][rowA][ka+2]=bv0.z; Bs[0][rowA][ka+3]=bv0.w;
        Bs[0][rowA+64][ka+0]=bv1.x; Bs[0][rowA+64][ka+1]=bv1.y; Bs[0][rowA+64][ka+2]=bv1.z; Bs[0][rowA+64][ka+3]=bv1.w;
        Bs[0][rowA+128][ka+0]=bv2.x; Bs[0][rowA+128][ka+1]=bv2.y; Bs[0][rowA+128][ka+2]=bv2.z; Bs[0][rowA+128][ka+3]=bv2.w;
    }
    __syncthreads();
    const int KT = K >> 4;
    int p = 0;
    for (int kt = 0; kt < KT; kt++){
        float4 nav, nb0, nb1, nb2;
        if (kt < KT-1){
            nav = *(const float4*)(pA  + (kt+1)*16);
            nb0 = *(const float4*)(pB0 + (kt+1)*16);
            nb1 = *(const float4*)(pB1 + (kt+1)*16);
            nb2 = *(const float4*)(pB2 + (kt+1)*16);
        }
        #pragma unroll
        for (int ks = 0; ks < 2; ks++){
            const int k0 = ks*8;
            unsigned a[2][4];
            #pragma unroll
            for (int mi = 0; mi < 2; mi++){
                int mr = m_w + mi*16;
                a[mi][0] = tf32r(As[p][mr+g][k0+t]);
                a[mi][1] = tf32r(As[p][mr+8+g][k0+t]);
                a[mi][2] = tf32r(As[p][mr+g][k0+t+4]);
                a[mi][3] = tf32r(As[p][mr+8+g][k0+t+4]);
            }
            unsigned b[6][2];
            #pragma unroll
            for (int ni = 0; ni < 6; ni++){
                int nr = n_w + ni*8 + g;
                b[ni][0] = tf32r(Bs[p][nr][k0+t]);
                b[ni][1] = tf32r(Bs[p][nr][k0+t+4]);
            }
            #pragma unroll
            for (int mi = 0; mi < 2; mi++)
                #pragma unroll
                for (int ni = 0; ni < 6; ni++)
                    mma8(c[mi][ni], a[mi], b[ni]);
        }
        if (kt < KT-1){
            int q = 1-p;
            As[q][rowA][ka+0]=nav.x; As[q][rowA][ka+1]=nav.y; As[q][rowA][ka+2]=nav.z; As[q][rowA][ka+3]=nav.w;
            Bs[q][rowA][ka+0]=nb0.x; Bs[q][rowA][ka+1]=nb0.y; Bs[q][rowA][ka+2]=nb0.z; Bs[q][rowA][ka+3]=nb0.w;
            Bs[q][rowA+64][ka+0]=nb1.x; Bs[q][rowA+64][ka+1]=nb1.y; Bs[q][rowA+64][ka+2]=nb1.z; Bs[q][rowA+64][ka+3]=nb1.w;
            Bs[q][rowA+128][ka+0]=nb2.x; Bs[q][rowA+128][ka+1]=nb2.y; Bs[q][rowA+128][ka+2]=nb2.z; Bs[q][rowA+128][ka+3]=nb2.w;
            __syncthreads();
        }
        p ^= 1;
    }
    float2 bb[6];
    #pragma unroll
    for (int ni = 0; ni < 6; ni++){
        int col = n_w + ni*8 + t*2;
        bb[ni] = *(const float2*)(bias + col);
        #pragma unroll
        for (int mi = 0; mi < 2; mi++){
            c[mi][ni][0] += bb[ni].x; c[mi][ni][1] += bb[ni].y;
            c[mi][ni][2] += bb[ni].x; c[mi][ni][3] += bb[ni].y;
        }
    }
    #pragma unroll
    for (int mi = 0; mi < 2; mi++){
        float s0=0,q0=0,s1=0,q1=0;
        #pragma unroll
        for (int ni = 0; ni < 6; ni++){
            s0 += c[mi][ni][0] + c[mi][ni][1];
            q0 += c[mi][ni][0]*c[mi][ni][0] + c[mi][ni][1]*c[mi][ni][1];
            s1 += c[mi][ni][2] + c[mi][ni][3];
            q1 += c[mi][ni][2]*c[mi][ni][2] + c[mi][ni][3]*c[mi][ni][3];
        }
        #pragma unroll
        for (int off = 1; off <= 2; off <<= 1){
            s0 += __shfl_xor_sync(0xffffffffu, s0, off);
            q0 += __shfl_xor_sync(0xffffffffu, q0, off);
            s1 += __shfl_xor_sync(0xffffffffu, s1, off);
            q1 += __shfl_xor_sync(0xffffffffu, q1, off);
        }
        if (t == 0){
            int r0 = m_w + mi*16 + g;
            red_s[r0][warp_n] = s0; red_q[r0][warp_n] = q0;
            red_s[r0+8][warp_n] = s1; red_q[r0+8][warp_n] = q1;
        }
    }
    __syncthreads();
    const float invC = 1.0f / 192.0f;
    #pragma unroll
    for (int mi = 0; mi < 2; mi++){
        #pragma unroll
        for (int half = 0; half < 2; half++){
            int row = m_w + mi*16 + half*8 + g;
            float s = red_s[row][0] + red_s[row][1] + red_s[row][2] + red_s[row][3];
            float q = red_q[row][0] + red_q[row][1] + red_q[row][2] + red_q[row][3];
            float mean = s * invC;
            float var  = q * invC - mean*mean;
            float rstd = rsqrtf(var + 1e-5f);
            long gi = PIX ? (long)rpix[row] : (long)(m0 + row)*CH;
            #pragma unroll
            for (int ni = 0; ni < 6; ni++){
                int col = n_w + ni*8 + t*2;
                float y0 = c[mi][ni][half*2+0];
                float y1 = c[mi][ni][half*2+1];
                float2 rv = *(const float2*)(res + gi + col);
                float2 wv = *(const float2*)(nw + col);
                float2 bn = *(const float2*)(nb + col);
                float2 o;
                o.x = rv.x + (y0 - mean)*rstd*wv.x + bn.x;
                o.y = rv.y + (y1 - mean)*rstd*wv.y + bn.y;
                *(float2*)(out + gi + col) = o;
            }
        }
    }
}

// ---------------- kernel 4: fc1 GEMM + fast GELU ----------------
__global__ __launch_bounds__(256)
void fc1_kernel(const float* __restrict__ w, const float* __restrict__ bias){
    __shared__ float As[2][128][20];
    __shared__ float Bs[2][128][20];
    const int tid  = threadIdx.x;
    const int m0   = blockIdx.x * 128;
    const int n0   = blockIdx.y * 128;
    const int warp = tid >> 5, lane = tid & 31;
    const int g = lane >> 2, t = lane & 3;
    const int warp_m = warp & 3, warp_n = warp >> 2;
    const int m_w = warp_m*32, n_w = warp_n*64;
    const int rowA = tid >> 1, ka = (tid & 1) * 8;
    float c[2][8][4];
    #pragma unroll
    for (int i=0;i<2;i++) for (int j=0;j<8;j++) for (int q=0;q<4;q++) c[i][j][q]=0.f;

    const float* pA = g_x1 + (long)(m0 + rowA)*CH + ka;
    const float* pB = w + (long)(n0 + rowA)*CH + ka;
    {
        float4 a0 = *(const float4*)(pA);
        float4 a1 = *(const float4*)(pA + 4);
        float4 b0 = *(const float4*)(pB);
        float4 b1 = *(const float4*)(pB + 4);
        As[0][rowA][ka+0]=a0.x; As[0][rowA][ka+1]=a0.y; As[0][rowA][ka+2]=a0.z; As[0][rowA][ka+3]=a0.w;
        As[0][rowA][ka+4]=a1.x; As[0][rowA][ka+5]=a1.y; As[0][rowA][ka+6]=a1.z; As[0][rowA][ka+7]=a1.w;
        Bs[0][rowA][ka+0]=b0.x; Bs[0][rowA][ka+1]=b0.y; Bs[0][rowA][ka+2]=b0.z; Bs[0][rowA][ka+3]=b0.w;
        Bs[0][rowA][ka+4]=b1.x; Bs[0][rowA][ka+5]=b1.y; Bs[0][rowA][ka+6]=b1.z; Bs[0][rowA][ka+7]=b1.w;
    }
    __syncthreads();
    int p = 0;
    for (int kt = 0; kt < 12; kt++){
        float4 na0, na1, nb0, nb1;
        if (kt < 11){
            na0 = *(const float4*)(pA + (kt+1)*16);
            na1 = *(const float4*)(pA + (kt+1)*16 + 4);
            nb0 = *(const float4*)(pB + (kt+1)*16);
            nb1 = *(const float4*)(pB + (kt+1)*16 + 4);
        }
        #pragma unroll
        for (int ks = 0; ks < 2; ks++){
            const int k0 = ks*8;
            unsigned a[2][4];
            #pragma unroll
            for (int mi = 0; mi < 2; mi++){
                int mr = m_w + mi*16;
                a[mi][0] = tf32r(As[p][mr+g][k0+t]);
                a[mi][1] = tf32r(As[p][mr+8+g][k0+t]);
                a[mi][2] = tf32r(As[p][mr+g][k0+t+4]);
                a[mi][3] = tf32r(As[p][mr+8+g][k0+t+4]);
            }
            unsigned b[8][2];
            #pragma unroll
            for (int ni = 0; ni < 8; ni++){
                int nr = n_w + ni*8 + g;
                b[ni][0] = tf32r(Bs[p][nr][k0+t]);
                b[ni][1] = tf32r(Bs[p][nr][k0+t+4]);
            }
            #pragma unroll
            for (int mi = 0; mi < 2; mi++)
                #pragma unroll
                for (int ni = 0; ni < 8; ni++)
                    mma8(c[mi][ni], a[mi], b[ni]);
        }
        if (kt < 11){
            int q = 1-p;
            As[q][rowA][ka+0]=na0.x; As[q][rowA][ka+1]=na0.y; As[q][rowA][ka+2]=na0.z; As[q][rowA][ka+3]=na0.w;
            As[q][rowA][ka+4]=na1.x; As[q][rowA][ka+5]=na1.y; As[q][rowA][ka+6]=na1.z; As[q][rowA][ka+7]=na1.w;
            Bs[q][rowA][ka+0]=nb0.x; Bs[q][rowA][ka+1]=nb0.y; Bs[q][rowA][ka+2]=nb0.z; Bs[q][rowA][ka+3]=nb0.w;
            Bs[q][rowA][ka+4]=nb1.x; Bs[q][rowA][ka+5]=nb1.y; Bs[q][rowA][ka+6]=nb1.z; Bs[q][rowA][ka+7]=nb1.w;
            __syncthreads();
        }
        p ^= 1;
    }
    #pragma unroll
    for (int mi = 0; mi < 2; mi++){
        #pragma unroll
        for (int ni = 0; ni < 8; ni++){
            int col = n0 + n_w + ni*8 + t*2;
            float2 bv = *(const float2*)(bias + col);
            int r0 = m0 + m_w + mi*16 + g;
            float2 o0, o1;
            o0.x = gelu_fast(c[mi][ni][0] + bv.x);
            o0.y = gelu_fast(c[mi][ni][1] + bv.y);
            o1.x = gelu_fast(c[mi][ni][2] + bv.x);
            o1.y = gelu_fast(c[mi][ni][3] + bv.y);
            *(float2*)(g_hidden + (long)r0*MLPH + col) = o0;
            *(float2*)(g_hidden + (long)(r0+8)*MLPH + col) = o1;
        }
    }
}

// ---------------- launch ----------------
extern "C" void kernel_launch(void* const* d_in, const int* in_sizes, int n_in,
                              void* d_out, int out_size){
    const float* x        = (const float*)d_in[0];
    const float* qkv_w    = (const float*)d_in[1];
    const float* qkv_b    = (const float*)d_in[2];
    const float* proj_w   = (const float*)d_in[3];
    const float* proj_b   = (const float*)d_in[4];
    const float* lscale   = (const float*)d_in[5];
    const float* cpb_w1   = (const float*)d_in[6];
    const float* cpb_b1   = (const float*)d_in[7];
    const float* cpb_w2   = (const float*)d_in[8];
    const float* norm1_w  = (const float*)d_in[9];
    const float* norm1_b  = (const float*)d_in[10];
    const float* norm2_w  = (const float*)d_in[11];
    const float* norm2_b  = (const float*)d_in[12];
    const float* fc1_w    = (const float*)d_in[13];
    const float* fc1_b    = (const float*)d_in[14];
    const float* fc2_w    = (const float*)d_in[15];
    const float* fc2_b    = (const float*)d_in[16];
    float* out = (float*)d_out;

    float *p_attnout, *p_x1, *p_hidden;
    cudaGetSymbolAddress((void**)&p_attnout, g_attnout);
    cudaGetSymbolAddress((void**)&p_x1, g_x1);
    cudaGetSymbolAddress((void**)&p_hidden, g_hidden);

    cpb_kernel<<<1, 256>>>(cpb_w1, cpb_b1, cpb_w2);
    qkv_kernel<true><<<dim3(MROWS/128, 6), 256>>>(x, qkv_w, qkv_b, 0);
    qkv_kernel<false><<<dim3(MROWS/128, 3), 256>>>(x, qkv_w, qkv_b, 6);
    attn_kernel<<<dim3(BW, HEADS), 256>>>(lscale);
    gemm_ln_kernel<true><<<MROWS/64, 256>>>(p_attnout, proj_w, proj_b,
                                            norm1_w, norm1_b, x, p_x1, CH);
    fc1_kernel<<<dim3(MROWS/128, MLPH/128), 256>>>(fc1_w, fc1_b);
    gemm_ln_kernel<false><<<MROWS/64, 256>>>(p_hidden, fc2_w, fc2_b,
                                             norm2_w, norm2_b, p_x1, out, MLPH);
}

// round 17
// speedup vs baseline: 1.0107x; 1.0107x over previous
#include <cuda_runtime.h>
#include <math.h>

// ---------------- problem constants ----------------
#define BATCH   32
#define IMGHW   56
#define CH      192
#define HEADS   6
#define HDIM    32
#define WSZ     7
#define NTOK    49
#define NWIN    64
#define BW      (BATCH*NWIN)     // 2048 windows
#define MROWS   (BW*NTOK)        // 100352 tokens
#define MLPH    768

// ---------------- scratch ----------------
__device__ float g_q[BW*HEADS*NTOK*HDIM];
__device__ float g_k[BW*HEADS*NTOK*HDIM];
__device__ float g_v[BW*HEADS*NTOK*HDIM];
__device__ float g_attnout[MROWS*CH];
__device__ float g_x1[MROWS*CH];
__device__ float g_hidden[MROWS*MLPH];
__device__ float g_rpb[HEADS*NTOK*NTOK];

__device__ __forceinline__ int row_to_pix(int m){
    int b_ = m / NTOK;
    int nn = m - b_*NTOK;
    int b  = b_ >> 6;
    int w  = b_ & 63;
    int wh = w >> 3, ww = w & 7;
    int r  = nn / 7, c = nn - r*7;
    int h  = wh*7 + r + 3; if (h >= IMGHW) h -= IMGHW;
    int x  = ww*7 + c + 3; if (x >= IMGHW) x -= IMGHW;
    return ((b*IMGHW + h)*IMGHW + x)*CH;
}

// ---------------- tf32 helpers ----------------
__device__ __forceinline__ unsigned tf32r(float x){
    unsigned u; asm("cvt.rna.tf32.f32 %0, %1;" : "=r"(u) : "f"(x)); return u;
}
__device__ __forceinline__ void mma8(float* c, const unsigned* a, const unsigned* b){
    asm volatile("mma.sync.aligned.m16n8k8.row.col.f32.tf32.tf32.f32 "
        "{%0,%1,%2,%3},{%4,%5,%6,%7},{%8,%9},{%0,%1,%2,%3};"
        : "+f"(c[0]), "+f"(c[1]), "+f"(c[2]), "+f"(c[3])
        : "r"(a[0]), "r"(a[1]), "r"(a[2]), "r"(a[3]), "r"(b[0]), "r"(b[1]));
}

// fast erf (Abramowitz & Stegun 7.1.26, |err| < 1.5e-7)
__device__ __forceinline__ float erf_fast(float x){
    float ax = fabsf(x);
    float t  = 1.0f / (1.0f + 0.3275911f * ax);
    float p  = t*(0.254829592f + t*(-0.284496736f + t*(1.421413741f +
               t*(-1.453152027f + t*1.061405429f))));
    float e  = 1.0f - p * __expf(-ax*ax);
    return copysignf(e, x);
}
__device__ __forceinline__ float gelu_fast(float x){
    return x * 0.5f * (1.0f + erf_fast(x * 0.70710678118654752f));
}

// ---------------- kernel 0: CPB MLP -> bias table ----------------
__global__ __launch_bounds__(256)
void cpb_kernel(const float* __restrict__ w1, const float* __restrict__ b1,
                const float* __restrict__ w2){
    __shared__ float tbl[169*HEADS];
    const int tid = threadIdx.x;
    if (tid < 169){
        int dh = tid / 13, dw = tid - 13*(tid/13);
        float th = (float)(dh - 6) / 6.0f * 7.0f;
        float tw = (float)(dw - 6) / 6.0f * 7.0f;
        float sh = (th > 0.f) ? 1.f : ((th < 0.f) ? -1.f : 0.f);
        float sw = (tw > 0.f) ? 1.f : ((tw < 0.f) ? -1.f : 0.f);
        const float inv_log2_7 = 1.0f / log2f(7.0f);
        th = sh * log2f(fabsf(th) + 1.0f) * inv_log2_7;
        tw = sw * log2f(fabsf(tw) + 1.0f) * inv_log2_7;
        float acc[HEADS];
        #pragma unroll
        for (int h = 0; h < HEADS; h++) acc[h] = 0.f;
        for (int j = 0; j < 512; j++){
            float hv = w1[j*2]*th + w1[j*2+1]*tw + b1[j];
            hv = (hv > 0.f) ? hv : 0.01f*hv;
            #pragma unroll
            for (int h = 0; h < HEADS; h++) acc[h] += w2[h*512 + j] * hv;
        }
        #pragma unroll
        for (int h = 0; h < HEADS; h++) tbl[tid*HEADS + h] = acc[h];
    }
    __syncthreads();
    for (int p = tid; p < HEADS*NTOK*NTOK; p += 256){
        int h   = p / (NTOK*NTOK);
        int rem = p - h*(NTOK*NTOK);
        int i   = rem / NTOK, j = rem - i*NTOK;
        int dh  = i/7 - j/7 + 6;
        int dw  = (i - 7*(i/7)) - (j - 7*(j/7)) + 6;
        float v = tbl[(dh*13 + dw)*HEADS + h];
        g_rpb[p] = 14.0f / (1.0f + expf(-v));
    }
}

// ---------------- kernel 1: QKV GEMM, pipelined ----------------
// SPLIT3=true: 3xTF32 hi/lo split (q,k columns). false: single-pass (v columns).
template<bool SPLIT3>
__global__ __launch_bounds__(256)
void qkv_kernel(const float* __restrict__ x, const float* __restrict__ w,
                const float* __restrict__ bias, int ny0){
    __shared__ float As[2][128][20];
    __shared__ float Bs[2][64][20];
    __shared__ int rpix[128];
    __shared__ int rq[128];
    const int tid  = threadIdx.x;
    const int m0   = blockIdx.x * 128;
    const int n0   = (blockIdx.y + ny0) * 64;
    const int warp = tid >> 5, lane = tid & 31;
    const int g = lane >> 2, t = lane & 3;
    const int warp_m = warp & 3, warp_n = warp >> 2;
    const int m_w = warp_m*32, n_w = warp_n*32;
    if (tid < 128){
        int m = m0 + tid;
        rpix[tid] = row_to_pix(m);
        int b_ = m / NTOK; int nn = m - b_*NTOK;
        rq[tid] = b_*(HEADS*NTOK*HDIM) + nn*HDIM;
    }
    const int rowA = tid >> 1, ka = (tid & 1) * 8;
    const int rowB = tid >> 2, kb = (tid & 3) * 4;
    float c[2][4][4];
    #pragma unroll
    for (int i=0;i<2;i++) for (int j=0;j<4;j++) for (int q=0;q<4;q++) c[i][j][q]=0.f;
    __syncthreads();
    const float* pA = x + rpix[rowA] + ka;
    const float* pB = w + (n0 + rowB)*CH + kb;
    {
        float4 a0 = *(const float4*)(pA);
        float4 a1 = *(const float4*)(pA + 4);
        float4 bv = *(const float4*)(pB);
        As[0][rowA][ka+0]=a0.x; As[0][rowA][ka+1]=a0.y; As[0][rowA][ka+2]=a0.z; As[0][rowA][ka+3]=a0.w;
        As[0][rowA][ka+4]=a1.x; As[0][rowA][ka+5]=a1.y; As[0][rowA][ka+6]=a1.z; As[0][rowA][ka+7]=a1.w;
        Bs[0][rowB][kb+0]=bv.x; Bs[0][rowB][kb+1]=bv.y; Bs[0][rowB][kb+2]=bv.z; Bs[0][rowB][kb+3]=bv.w;
    }
    __syncthreads();
    int p = 0;
    for (int kt = 0; kt < 12; kt++){
        float4 na0, na1, nbv;
        if (kt < 11){
            na0 = *(const float4*)(pA + (kt+1)*16);
            na1 = *(const float4*)(pA + (kt+1)*16 + 4);
            nbv = *(const float4*)(pB + (kt+1)*16);
        }
        #pragma unroll
        for (int ks = 0; ks < 2; ks++){
            const int k0 = ks*8;
            if (SPLIT3){
                unsigned ah[2][4], al[2][4];
                #pragma unroll
                for (int mi = 0; mi < 2; mi++){
                    int mr = m_w + mi*16;
                    float f;
                    f = As[p][mr+g][k0+t];     ah[mi][0]=tf32r(f); al[mi][0]=tf32r(f-__uint_as_float(ah[mi][0]));
                    f = As[p][mr+8+g][k0+t];   ah[mi][1]=tf32r(f); al[mi][1]=tf32r(f-__uint_as_float(ah[mi][1]));
                    f = As[p][mr+g][k0+t+4];   ah[mi][2]=tf32r(f); al[mi][2]=tf32r(f-__uint_as_float(ah[mi][2]));
                    f = As[p][mr+8+g][k0+t+4]; ah[mi][3]=tf32r(f); al[mi][3]=tf32r(f-__uint_as_float(ah[mi][3]));
                }
                unsigned bh[4][2], bl[4][2];
                #pragma unroll
                for (int ni = 0; ni < 4; ni++){
                    int nr = n_w + ni*8 + g;
                    float f;
                    f = Bs[p][nr][k0+t];   bh[ni][0]=tf32r(f); bl[ni][0]=tf32r(f-__uint_as_float(bh[ni][0]));
                    f = Bs[p][nr][k0+t+4]; bh[ni][1]=tf32r(f); bl[ni][1]=tf32r(f-__uint_as_float(bh[ni][1]));
                }
                #pragma unroll
                for (int mi = 0; mi < 2; mi++)
                    #pragma unroll
                    for (int ni = 0; ni < 4; ni++){
                        mma8(c[mi][ni], al[mi], bh[ni]);
                        mma8(c[mi][ni], ah[mi], bl[ni]);
                        mma8(c[mi][ni], ah[mi], bh[ni]);
                    }
            } else {
                unsigned a[2][4];
                #pragma unroll
                for (int mi = 0; mi < 2; mi++){
                    int mr = m_w + mi*16;
                    a[mi][0] = tf32r(As[p][mr+g][k0+t]);
                    a[mi][1] = tf32r(As[p][mr+8+g][k0+t]);
                    a[mi][2] = tf32r(As[p][mr+g][k0+t+4]);
                    a[mi][3] = tf32r(As[p][mr+8+g][k0+t+4]);
                }
                unsigned b[4][2];
                #pragma unroll
                for (int ni = 0; ni < 4; ni++){
                    int nr = n_w + ni*8 + g;
                    b[ni][0] = tf32r(Bs[p][nr][k0+t]);
                    b[ni][1] = tf32r(Bs[p][nr][k0+t+4]);
                }
                #pragma unroll
                for (int mi = 0; mi < 2; mi++)
                    #pragma unroll
                    for (int ni = 0; ni < 4; ni++)
                        mma8(c[mi][ni], a[mi], b[ni]);
            }
        }
        if (kt < 11){
            int q = 1-p;
            As[q][rowA][ka+0]=na0.x; As[q][rowA][ka+1]=na0.y; As[q][rowA][ka+2]=na0.z; As[q][rowA][ka+3]=na0.w;
            As[q][rowA][ka+4]=na1.x; As[q][rowA][ka+5]=na1.y; As[q][rowA][ka+6]=na1.z; As[q][rowA][ka+7]=na1.w;
            Bs[q][rowB][kb+0]=nbv.x; Bs[q][rowB][kb+1]=nbv.y; Bs[q][rowB][kb+2]=nbv.z; Bs[q][rowB][kb+3]=nbv.w;
            __syncthreads();
        }
        p ^= 1;
    }
    #pragma unroll
    for (int mi = 0; mi < 2; mi++){
        #pragma unroll
        for (int ni = 0; ni < 4; ni++){
            int col  = n0 + n_w + ni*8 + t*2;
            int slot = col / 192;
            int rem  = col - slot*192;
            float* dst = (slot == 0) ? g_q : ((slot == 1) ? g_k : g_v);
            int off = (rem >> 5)*(NTOK*HDIM) + (rem & 31);
            float2 bv = *(const float2*)(bias + col);
            int r0 = m_w + mi*16 + g;
            float2 o0 = {c[mi][ni][0] + bv.x, c[mi][ni][1] + bv.y};
            *(float2*)(dst + rq[r0] + off) = o0;
            float2 o1 = {c[mi][ni][2] + bv.x, c[mi][ni][3] + bv.y};
            *(float2*)(dst + rq[r0+8] + off) = o1;
        }
    }
}

// ---------------- kernel 2: windowed attention, tensor-core + parallel softmax ----------------
// One block per (window, head). 256 threads, 8 warps.
__global__ __launch_bounds__(256)
void attn_kernel(const float* __restrict__ logit_scale){
    __shared__ float qs[64*36];        // [n][d]
    __shared__ float ks[64*36];
    __shared__ float vs[64*40];        // [j][d]
    __shared__ float S[64*68];         // [i][j]
    __shared__ int lab[64];
    const int b_   = blockIdx.x;
    const int head = blockIdx.y;
    const int tid  = threadIdx.x;
    const int warp = tid >> 5, lane = tid & 31;
    const int g = lane >> 2, t = lane & 3;
    const float* qg = g_q + (b_*HEADS + head)*NTOK*HDIM;
    const float* kg = g_k + (b_*HEADS + head)*NTOK*HDIM;
    const float* vg = g_v + (b_*HEADS + head)*NTOK*HDIM;

    for (int idx = tid; idx < 64*32; idx += 256){
        int n = idx >> 5, d = idx & 31;
        bool ok = (n < NTOK);
        float qv = ok ? qg[n*HDIM + d] : 0.f;
        float kv = ok ? kg[n*HDIM + d] : 0.f;
        float vv = ok ? vg[n*HDIM + d] : 0.f;
        qs[n*36 + d] = qv;
        ks[n*36 + d] = kv;
        vs[n*40 + d] = vv;
    }
    if (tid < 64){
        int w  = b_ & 63;
        int wh = w >> 3, ww = w & 7;
        int r  = tid / 7, c = tid - 7*(tid/7);
        int hp = wh*7 + r, wp = ww*7 + c;
        int rb = (hp < 49) ? 0 : ((hp < 53) ? 1 : 2);
        int cb = (wp < 49) ? 0 : ((wp < 53) ? 1 : 2);
        lab[tid] = (tid < NTOK) ? (rb*3 + cb) : -1;
    }
    __syncthreads();
    // normalize q,k: 2 threads per row, 128 rows. Convergent: all 256 threads shfl.
    {
        int row  = tid >> 1;            // 0..127
        int half = tid & 1;
        float* base = ((row < 64) ? qs + row*36 : ks + (row-64)*36) + half*16;
        float ss = 0.f;
        #pragma unroll
        for (int d = 0; d < 16; d++){ float v = base[d]; ss += v*v; }
        ss += __shfl_xor_sync(0xffffffffu, ss, 1);
        float inv = 1.0f / fmaxf(sqrtf(ss), 1e-12f);
        #pragma unroll
        for (int d = 0; d < 16; d++) base[d] *= inv;
    }
    __syncthreads();
    // S = qn @ kn^T  (3xTF32). warp: rows 16*(w&3), cols 32*(w>>2)
    {
        const int mt = (warp & 3) * 16;
        const int nt = (warp >> 2) * 32;
        float c[4][4];
        #pragma unroll
        for (int i=0;i<4;i++) for (int j=0;j<4;j++) c[i][j]=0.f;
        #pragma unroll
        for (int k0 = 0; k0 < 32; k0 += 8){
            unsigned ah[4], al[4];
            float f;
            f = qs[(mt+g)*36 + k0+t];     ah[0]=tf32r(f); al[0]=tf32r(f-__uint_as_float(ah[0]));
            f = qs[(mt+8+g)*36 + k0+t];   ah[1]=tf32r(f); al[1]=tf32r(f-__uint_as_float(ah[1]));
            f = qs[(mt+g)*36 + k0+t+4];   ah[2]=tf32r(f); al[2]=tf32r(f-__uint_as_float(ah[2]));
            f = qs[(mt+8+g)*36 + k0+t+4]; ah[3]=tf32r(f); al[3]=tf32r(f-__uint_as_float(ah[3]));
            #pragma unroll
            for (int ni = 0; ni < 4; ni++){
                int nr = nt + ni*8 + g;
                unsigned bh[2], bl[2];
                f = ks[nr*36 + k0+t];   bh[0]=tf32r(f); bl[0]=tf32r(f-__uint_as_float(bh[0]));
                f = ks[nr*36 + k0+t+4]; bh[1]=tf32r(f); bl[1]=tf32r(f-__uint_as_float(bh[1]));
                mma8(c[ni], al, bh);
                mma8(c[ni], ah, bl);
                mma8(c[ni], ah, bh);
            }
        }
        #pragma unroll
        for (int ni = 0; ni < 4; ni++){
            int col = nt + ni*8 + 2*t;
            *(float2*)&S[(mt+g)*68 + col]   = make_float2(c[ni][0], c[ni][1]);
            *(float2*)&S[(mt+8+g)*68 + col] = make_float2(c[ni][2], c[ni][3]);
        }
    }
    __syncthreads();
    // softmax: 4 threads per row, 64 rows. CONVERGENT: every thread executes both shfls;
    // validity folded into data (padded rows write zeros, no div-by-0 NaN).
    {
        int r  = tid >> 2;      // 0..63
        int t4 = tid & 3;
        float* row = S + r*68;
        bool vr = (r < NTOK);
        const float sc = expf(fminf(logit_scale[head], 4.60517019f));
        const float* rpb = g_rpb + head*NTOK*NTOK + (vr ? r : 0)*NTOK;
        int li = vr ? lab[r] : 0;
        int j0 = t4*16;
        float vv[16];
        float mx = -1e30f;
        #pragma unroll
        for (int jj = 0; jj < 16; jj++){
            int j = j0 + jj;
            if (vr && j < NTOK){
                float mval = (li == lab[j]) ? 0.f : -100.f;
                float v = row[j]*sc + rpb[j] + mval;
                vv[jj] = v;
                mx = fmaxf(mx, v);
            } else vv[jj] = -1e30f;
        }
        mx = fmaxf(mx, __shfl_xor_sync(0xffffffffu, mx, 1));
        mx = fmaxf(mx, __shfl_xor_sync(0xffffffffu, mx, 2));
        float sum = 0.f;
        float ee[16];
        #pragma unroll
        for (int jj = 0; jj < 16; jj++){
            int j = j0 + jj;
            float e = (vr && j < NTOK) ? __expf(vv[jj] - mx) : 0.f;
            ee[jj] = e;
            sum += e;
        }
        sum += __shfl_xor_sync(0xffffffffu, sum, 1);
        sum += __shfl_xor_sync(0xffffffffu, sum, 2);
        float inv = vr ? (1.0f / sum) : 0.f;
        #pragma unroll
        for (int jj = 0; jj < 16; jj++) row[j0 + jj] = ee[jj] * inv;
    }
    __syncthreads();
    // O = P @ V  (P split hi/lo, V single tf32). warp: rows 16*(w&3), cols 16*(w>>2)
    {
        const int mt = (warp & 3) * 16;
        const int nh = (warp >> 2) * 16;
        float c[2][4];
        #pragma unroll
        for (int i=0;i<2;i++) for (int j=0;j<4;j++) c[i][j]=0.f;
        #pragma unroll
        for (int k0 = 0; k0 < 64; k0 += 8){
            unsigned ah[4], al[4];
            float f;
            f = S[(mt+g)*68 + k0+t];     ah[0]=tf32r(f); al[0]=tf32r(f-__uint_as_float(ah[0]));
            f = S[(mt+8+g)*68 + k0+t];   ah[1]=tf32r(f); al[1]=tf32r(f-__uint_as_float(ah[1]));
            f = S[(mt+g)*68 + k0+t+4];   ah[2]=tf32r(f); al[2]=tf32r(f-__uint_as_float(ah[2]));
            f = S[(mt+8+g)*68 + k0+t+4]; ah[3]=tf32r(f); al[3]=tf32r(f-__uint_as_float(ah[3]));
            #pragma unroll
            for (int ni = 0; ni < 2; ni++){
                unsigned b[2];
                b[0] = tf32r(vs[(k0+t)*40 + nh + ni*8 + g]);
                b[1] = tf32r(vs[(k0+t+4)*40 + nh + ni*8 + g]);
                mma8(c[ni], ah, b);
                mma8(c[ni], al, b);
            }
        }
        float* outb = g_attnout + (long)(b_*NTOK)*CH + head*HDIM;
        int r0 = mt + g, r1 = mt + 8 + g;
        #pragma unroll
        for (int ni = 0; ni < 2; ni++){
            int col = nh + ni*8 + 2*t;
            if (r0 < NTOK) *(float2*)&outb[r0*CH + col] = make_float2(c[ni][0], c[ni][1]);
            if (r1 < NTOK) *(float2*)&outb[r1*CH + col] = make_float2(c[ni][2], c[ni][3]);
        }
    }
}

// ---------------- kernels 3/5: GEMM(BMx192) + LN + residual (R4 version, runtime K) ----------------
template<bool PIX>
__global__ __launch_bounds__(256)
void gemm_ln_kernel(const float* __restrict__ A, const float* __restrict__ w,
                    const float* __restrict__ bias, const float* __restrict__ nw,
                    const float* __restrict__ nb, const float* __restrict__ res,
                    float* __restrict__ out, int K){
    __shared__ float As[2][64][20];
    __shared__ float Bs[2][192][20];
    __shared__ float red_s[64][4], red_q[64][4];
    __shared__ int rpix[64];
    const int tid  = threadIdx.x;
    const int m0   = blockIdx.x * 64;
    const int warp = tid >> 5, lane = tid & 31;
    const int g = lane >> 2, t = lane & 3;
    const int warp_m = warp >> 2, warp_n = warp & 3;
    const int m_w = warp_m*32, n_w = warp_n*48;
    if (PIX && tid < 64) rpix[tid] = row_to_pix(m0 + tid);
    const int rowA = tid >> 2, ka = (tid & 3) * 4;
    float c[2][6][4];
    #pragma unroll
    for (int i=0;i<2;i++) for (int j=0;j<6;j++) for (int q=0;q<4;q++) c[i][j][q]=0.f;

    const float* pA  = A + (long)(m0 + rowA)*K + ka;
    const float* pB0 = w + (long)(rowA      )*K + ka;
    const float* pB1 = w + (long)(rowA + 64 )*K + ka;
    const float* pB2 = w + (long)(rowA + 128)*K + ka;
    {
        float4 av  = *(const float4*)(pA);
        float4 bv0 = *(const float4*)(pB0);
        float4 bv1 = *(const float4*)(pB1);
        float4 bv2 = *(const float4*)(pB2);
        As[0][rowA][ka+0]=av.x; As[0][rowA][ka+1]=av.y; As[0][rowA][ka+2]=av.z; As[0][rowA][ka+3]=av.w;
        Bs[0][rowA][ka+0]=bv0.x; Bs[0][rowA][ka+1]=bv0.y; Bs[0][rowA][ka+2]=bv0.z; Bs[0][rowA][ka+3]=bv0.w;
        Bs[0][rowA+64][ka+0]=bv1.x; Bs[0][rowA+64][ka+1]=bv1.y; Bs[0][rowA+64][ka+2]=bv1.z; Bs[0][rowA+64][ka+3]=bv1.w;
        Bs[0][rowA+128][ka+0]=bv2.x; Bs[0][rowA+128][ka+1]=bv2.y; Bs[0][rowA+128][ka+2]=bv2.z; Bs[0][rowA+128][ka+3]=bv2.w;
    }
    __syncthreads();
    const int KT = K >> 4;
    int p = 0;
    for (int kt = 0; kt < KT; kt++){
        float4 nav, nb0, nb1, nb2;
        if (kt < KT-1){
            nav = *(const float4*)(pA  + (kt+1)*16);
            nb0 = *(const float4*)(pB0 + (kt+1)*16);
            nb1 = *(const float4*)(pB1 + (kt+1)*16);
            nb2 = *(const float4*)(pB2 + (kt+1)*16);
        }
        #pragma unroll
        for (int ks = 0; ks < 2; ks++){
            const int k0 = ks*8;
            unsigned a[2][4];
            #pragma unroll
            for (int mi = 0; mi < 2; mi++){
                int mr = m_w + mi*16;
                a[mi][0] = tf32r(As[p][mr+g][k0+t]);
                a[mi][1] = tf32r(As[p][mr+8+g][k0+t]);
                a[mi][2] = tf32r(As[p][mr+g][k0+t+4]);
                a[mi][3] = tf32r(As[p][mr+8+g][k0+t+4]);
            }
            unsigned b[6][2];
            #pragma unroll
            for (int ni = 0; ni < 6; ni++){
                int nr = n_w + ni*8 + g;
                b[ni][0] = tf32r(Bs[p][nr][k0+t]);
                b[ni][1] = tf32r(Bs[p][nr][k0+t+4]);
            }
            #pragma unroll
            for (int mi = 0; mi < 2; mi++)
                #pragma unroll
                for (int ni = 0; ni < 6; ni++)
                    mma8(c[mi][ni], a[mi], b[ni]);
        }
        if (kt < KT-1){
            int q = 1-p;
            As[q][rowA][ka+0]=nav.x; As[q][rowA][ka+1]=nav.y; As[q][rowA][ka+2]=nav.z; As[q][rowA][ka+3]=nav.w;
            Bs[q][rowA][ka+0]=nb0.x; Bs[q][rowA][ka+1]=nb0.y; Bs[q][rowA][ka+2]=nb0.z; Bs[q][rowA][ka+3]=nb0.w;
            Bs[q][rowA+64][ka+0]=nb1.x; Bs[q][rowA+64][ka+1]=nb1.y; Bs[q][rowA+64][ka+2]=nb1.z; Bs[q][rowA+64][ka+3]=nb1.w;
            Bs[q][rowA+128][ka+0]=nb2.x; Bs[q][rowA+128][ka+1]=nb2.y; Bs[q][rowA+128][ka+2]=nb2.z; Bs[q][rowA+128][ka+3]=nb2.w;
            __syncthreads();
        }
        p ^= 1;
    }
    float2 bb[6];
    #pragma unroll
    for (int ni = 0; ni < 6; ni++){
        int col = n_w + ni*8 + t*2;
        bb[ni] = *(const float2*)(bias + col);
        #pragma unroll
        for (int mi = 0; mi < 2; mi++){
            c[mi][ni][0] += bb[ni].x; c[mi][ni][1] += bb[ni].y;
            c[mi][ni][2] += bb[ni].x; c[mi][ni][3] += bb[ni].y;
        }
    }
    #pragma unroll
    for (int mi = 0; mi < 2; mi++){
        float s0=0,q0=0,s1=0,q1=0;
        #pragma unroll
        for (int ni = 0; ni < 6; ni++){
            s0 += c[mi][ni][0] + c[mi][ni][1];
            q0 += c[mi][ni][0]*c[mi][ni][0] + c[mi][ni][1]*c[mi][ni][1];
            s1 += c[mi][ni][2] + c[mi][ni][3];
            q1 += c[mi][ni][2]*c[mi][ni][2] + c[mi][ni][3]*c[mi][ni][3];
        }
        #pragma unroll
        for (int off = 1; off <= 2; off <<= 1){
            s0 += __shfl_xor_sync(0xffffffffu, s0, off);
            q0 += __shfl_xor_sync(0xffffffffu, q0, off);
            s1 += __shfl_xor_sync(0xffffffffu, s1, off);
            q1 += __shfl_xor_sync(0xffffffffu, q1, off);
        }
        if (t == 0){
            int r0 = m_w + mi*16 + g;
            red_s[r0][warp_n] = s0; red_q[r0][warp_n] = q0;
            red_s[r0+8][warp_n] = s1; red_q[r0+8][warp_n] = q1;
        }
    }
    __syncthreads();
    const float invC = 1.0f / 192.0f;
    #pragma unroll
    for (int mi = 0; mi < 2; mi++){
        #pragma unroll
        for (int half = 0; half < 2; half++){
            int row = m_w + mi*16 + half*8 + g;
            float s = red_s[row][0] + red_s[row][1] + red_s[row][2] + red_s[row][3];
            float q = red_q[row][0] + red_q[row][1] + red_q[row][2] + red_q[row][3];
            float mean = s * invC;
            float var  = q * invC - mean*mean;
            float rstd = rsqrtf(var + 1e-5f);
            long gi = PIX ? (long)rpix[row] : (long)(m0 + row)*CH;
            #pragma unroll
            for (int ni = 0; ni < 6; ni++){
                int col = n_w + ni*8 + t*2;
                float y0 = c[mi][ni][half*2+0];
                float y1 = c[mi][ni][half*2+1];
                float2 rv = *(const float2*)(res + gi + col);
                float2 wv = *(const float2*)(nw + col);
                float2 bn = *(const float2*)(nb + col);
                float2 o;
                o.x = rv.x + (y0 - mean)*rstd*wv.x + bn.x;
                o.y = rv.y + (y1 - mean)*rstd*wv.y + bn.y;
                *(float2*)(out + gi + col) = o;
            }
        }
    }
}

// ---------------- kernel 4: fc1 GEMM + fast GELU ----------------
__global__ __launch_bounds__(256)
void fc1_kernel(const float* __restrict__ w, const float* __restrict__ bias){
    __shared__ float As[2][128][20];
    __shared__ float Bs[2][128][20];
    const int tid  = threadIdx.x;
    const int m0   = blockIdx.x * 128;
    const int n0   = blockIdx.y * 128;
    const int warp = tid >> 5, lane = tid & 31;
    const int g = lane >> 2, t = lane & 3;
    const int warp_m = warp & 3, warp_n = warp >> 2;
    const int m_w = warp_m*32, n_w = warp_n*64;
    const int rowA = tid >> 1, ka = (tid & 1) * 8;
    float c[2][8][4];
    #pragma unroll
    for (int i=0;i<2;i++) for (int j=0;j<8;j++) for (int q=0;q<4;q++) c[i][j][q]=0.f;

    const float* pA = g_x1 + (long)(m0 + rowA)*CH + ka;
    const float* pB = w + (long)(n0 + rowA)*CH + ka;
    {
        float4 a0 = *(const float4*)(pA);
        float4 a1 = *(const float4*)(pA + 4);
        float4 b0 = *(const float4*)(pB);
        float4 b1 = *(const float4*)(pB + 4);
        As[0][rowA][ka+0]=a0.x; As[0][rowA][ka+1]=a0.y; As[0][rowA][ka+2]=a0.z; As[0][rowA][ka+3]=a0.w;
        As[0][rowA][ka+4]=a1.x; As[0][rowA][ka+5]=a1.y; As[0][rowA][ka+6]=a1.z; As[0][rowA][ka+7]=a1.w;
        Bs[0][rowA][ka+0]=b0.x; Bs[0][rowA][ka+1]=b0.y; Bs[0][rowA][ka+2]=b0.z; Bs[0][rowA][ka+3]=b0.w;
        Bs[0][rowA][ka+4]=b1.x; Bs[0][rowA][ka+5]=b1.y; Bs[0][rowA][ka+6]=b1.z; Bs[0][rowA][ka+7]=b1.w;
    }
    __syncthreads();
    int p = 0;
    for (int kt = 0; kt < 12; kt++){
        float4 na0, na1, nb0, nb1;
        if (kt < 11){
            na0 = *(const float4*)(pA + (kt+1)*16);
            na1 = *(const float4*)(pA + (kt+1)*16 + 4);
            nb0 = *(const float4*)(pB + (kt+1)*16);
            nb1 = *(const float4*)(pB + (kt+1)*16 + 4);
        }
        #pragma unroll
        for (int ks = 0; ks < 2; ks++){
            const int k0 = ks*8;
            unsigned a[2][4];
            #pragma unroll
            for (int mi = 0; mi < 2; mi++){
                int mr = m_w + mi*16;
                a[mi][0] = tf32r(As[p][mr+g][k0+t]);
                a[mi][1] = tf32r(As[p][mr+8+g][k0+t]);
                a[mi][2] = tf32r(As[p][mr+g][k0+t+4]);
                a[mi][3] = tf32r(As[p][mr+8+g][k0+t+4]);
            }
            unsigned b[8][2];
            #pragma unroll
            for (int ni = 0; ni < 8; ni++){
                int nr = n_w + ni*8 + g;
                b[ni][0] = tf32r(Bs[p][nr][k0+t]);
                b[ni][1] = tf32r(Bs[p][nr][k0+t+4]);
            }
            #pragma unroll
            for (int mi = 0; mi < 2; mi++)
                #pragma unroll
                for (int ni = 0; ni < 8; ni++)
                    mma8(c[mi][ni], a[mi], b[ni]);
        }
        if (kt < 11){
            int q = 1-p;
            As[q][rowA][ka+0]=na0.x; As[q][rowA][ka+1]=na0.y; As[q][rowA][ka+2]=na0.z; As[q][rowA][ka+3]=na0.w;
            As[q][rowA][ka+4]=na1.x; As[q][rowA][ka+5]=na1.y; As[q][rowA][ka+6]=na1.z; As[q][rowA][ka+7]=na1.w;
            Bs[q][rowA][ka+0]=nb0.x; Bs[q][rowA][ka+1]=nb0.y; Bs[q][rowA][ka+2]=nb0.z; Bs[q][rowA][ka+3]=nb0.w;
            Bs[q][rowA][ka+4]=nb1.x; Bs[q][rowA][ka+5]=nb1.y; Bs[q][rowA][ka+6]=nb1.z; Bs[q][rowA][ka+7]=nb1.w;
            __syncthreads();
        }
        p ^= 1;
    }
    #pragma unroll
    for (int mi = 0; mi < 2; mi++){
        #pragma unroll
        for (int ni = 0; ni < 8; ni++){
            int col = n0 + n_w + ni*8 + t*2;
            float2 bv = *(const float2*)(bias + col);
            int r0 = m0 + m_w + mi*16 + g;
            float2 o0, o1;
            o0.x = gelu_fast(c[mi][ni][0] + bv.x);
            o0.y = gelu_fast(c[mi][ni][1] + bv.y);
            o1.x = gelu_fast(c[mi][ni][2] + bv.x);
            o1.y = gelu_fast(c[mi][ni][3] + bv.y);
            *(float2*)(g_hidden + (long)r0*MLPH + col) = o0;
            *(float2*)(g_hidden + (long)(r0+8)*MLPH + col) = o1;
        }
    }
}

// ---------------- launch ----------------
extern "C" void kernel_launch(void* const* d_in, const int* in_sizes, int n_in,
                              void* d_out, int out_size){
    const float* x        = (const float*)d_in[0];
    const float* qkv_w    = (const float*)d_in[1];
    const float* qkv_b    = (const float*)d_in[2];
    const float* proj_w   = (const float*)d_in[3];
    const float* proj_b   = (const float*)d_in[4];
    const float* lscale   = (const float*)d_in[5];
    const float* cpb_w1   = (const float*)d_in[6];
    const float* cpb_b1   = (const float*)d_in[7];
    const float* cpb_w2   = (const float*)d_in[8];
    const float* norm1_w  = (const float*)d_in[9];
    const float* norm1_b  = (const float*)d_in[10];
    const float* norm2_w  = (const float*)d_in[11];
    const float* norm2_b  = (const float*)d_in[12];
    const float* fc1_w    = (const float*)d_in[13];
    const float* fc1_b    = (const float*)d_in[14];
    const float* fc2_w    = (const float*)d_in[15];
    const float* fc2_b    = (const float*)d_in[16];
    float* out = (float*)d_out;

    float *p_attnout, *p_x1, *p_hidden;
    cudaGetSymbolAddress((void**)&p_attnout, g_attnout);
    cudaGetSymbolAddress((void**)&p_x1, g_x1);
    cudaGetSymbolAddress((void**)&p_hidden, g_hidden);

    cpb_kernel<<<1, 256>>>(cpb_w1, cpb_b1, cpb_w2);
    qkv_kernel<true><<<dim3(MROWS/128, 6), 256>>>(x, qkv_w, qkv_b, 0);
    qkv_kernel<false><<<dim3(MROWS/128, 3), 256>>>(x, qkv_w, qkv_b, 6);
    attn_kernel<<<dim3(BW, HEADS), 256>>>(lscale);
    gemm_ln_kernel<true><<<MROWS/64, 256>>>(p_attnout, proj_w, proj_b,
                                            norm1_w, norm1_b, x, p_x1, CH);
    fc1_kernel<<<dim3(MROWS/128, MLPH/128), 256>>>(fc1_w, fc1_b);
    gemm_ln_kernel<false><<<MROWS/64, 256>>>(p_hidden, fc2_w, fc2_b,
                                             norm2_w, norm2_b, p_x1, out, MLPH);
}